// round 15
// baseline (speedup 1.0000x reference)
#include <cuda_runtime.h>
#include <cuda_fp16.h>
#include <cstdint>

#define BN_EPS 1e-5f
#define MAXN 100000
#define MAXE 400000
#define MAXT 1000000

// ---- scratch (allocation-free, static device globals) ----
__device__ __half g_Vsrc[(size_t)MAXN * 256];  // [N,256] = [core_src | gate_src]
__device__ __half g_Vdst[(size_t)MAXN * 256];  // [N,256] = [core_dst | gate_dst]
__device__ __half g_Ep  [(size_t)MAXE * 256];  // [E,256] = [core_bond | gate_bond]
__device__ __half g_A   [(size_t)MAXT * 256];  // [T,256] fused core|gate (pre-BN)
__device__ __half g_seg [(size_t)MAXE * 128];  // segment sums (fp16x2 atomics)
__device__ float  g_stats[512];                // sumC | ssqC | sumG | ssqG
__device__ float  g_scale[512];                // aC | bC | aG | bG
__device__ float  g_Wv [512 * 128];            // [w_core_src; w_gate_src; w_core_dst; w_gate_dst]
__device__ float  g_Web[256 * 128];            // [w_core_bond ; w_gate_bond]
__device__ float  g_Wan[256 * 64];             // [w_core_angle ; w_gate_angle]

// ------------------------------------------------------------------
__global__ void zero_kernel(int E) {
    size_t n16 = (size_t)E * 16;
    size_t i = (size_t)blockIdx.x * blockDim.x + threadIdx.x;
    size_t st = (size_t)gridDim.x * blockDim.x;
    uint4 z = make_uint4(0, 0, 0, 0);
    uint4* p = reinterpret_cast<uint4*>(g_seg);
    for (size_t k = i; k < n16; k += st) p[k] = z;
}

// single preamble kernel: pack all weight pairs + zero stats.
__global__ void pack_all(const float* __restrict__ cs, const float* __restrict__ gs,
                         const float* __restrict__ cd, const float* __restrict__ gd,
                         const float* __restrict__ cb, const float* __restrict__ gb,
                         const float* __restrict__ ca, const float* __restrict__ ga) {
    int i = blockIdx.x * blockDim.x + threadIdx.x;  // grid 96*256 = 24576
    if (i < 512) g_stats[i] = 0.f;
    if (i < 16384) {
        g_Wv[i] = cs[i];           g_Wv[16384 + i] = gs[i];
        g_Wv[32768 + i] = cd[i];   g_Wv[49152 + i] = gd[i];
        g_Web[i] = cb[i];          g_Web[16384 + i] = gb[i];
    }
    if (i < 8192) {
        g_Wan[i] = ca[i];          g_Wan[8192 + i] = ga[i];
    }
}

// ---- fp16 helpers ----
__device__ __forceinline__ float4 ldh4(const __half* p) {
    uint2 u = *reinterpret_cast<const uint2*>(p);
    __half2 h0 = *reinterpret_cast<__half2*>(&u.x);
    __half2 h1 = *reinterpret_cast<__half2*>(&u.y);
    float2 f0 = __half22float2(h0);
    float2 f1 = __half22float2(h1);
    return make_float4(f0.x, f0.y, f1.x, f1.y);
}
__device__ __forceinline__ float4 f4add(float4 a, float4 b) {
    return make_float4(a.x + b.x, a.y + b.y, a.z + b.z, a.w + b.w);
}

// ------------------------------------------------------------------
// generic fp16 MMA sweep over 128x128 warp layout; strideW in words,
// K_STEPS k16-steps starting at word kwBase.
// ------------------------------------------------------------------
template<int K_STEPS>
__device__ __forceinline__
void mma_sweep(const __half* Xs, const __half* Ws, int strideW,
               float c[4][4][4], int warpM, int warpN, int g, int qc) {
    const uint32_t* Xu = reinterpret_cast<const uint32_t*>(Xs);
    const uint32_t* Wu = reinterpret_cast<const uint32_t*>(Ws);
#pragma unroll
    for (int s = 0; s < K_STEPS; ++s) {
        const int kw = s * 8;
        uint32_t a[4][4], b[4][2];
#pragma unroll
        for (int mf = 0; mf < 4; ++mf) {
            int r = warpM * 64 + mf * 16 + g;
            a[mf][0] = Xu[r * strideW + kw + qc];
            a[mf][1] = Xu[(r + 8) * strideW + kw + qc];
            a[mf][2] = Xu[r * strideW + kw + 4 + qc];
            a[mf][3] = Xu[(r + 8) * strideW + kw + 4 + qc];
        }
#pragma unroll
        for (int nf = 0; nf < 4; ++nf) {
            int n = warpN * 32 + nf * 8 + g;
            b[nf][0] = Wu[n * strideW + kw + qc];
            b[nf][1] = Wu[n * strideW + kw + 4 + qc];
        }
#pragma unroll
        for (int mf = 0; mf < 4; ++mf)
#pragma unroll
            for (int nf = 0; nf < 4; ++nf) {
                asm volatile(
                    "mma.sync.aligned.m16n8k16.row.col.f32.f16.f16.f32 "
                    "{%0,%1,%2,%3}, {%4,%5,%6,%7}, {%8,%9}, {%0,%1,%2,%3};"
                    : "+f"(c[mf][nf][0]), "+f"(c[mf][nf][1]),
                      "+f"(c[mf][nf][2]), "+f"(c[mf][nf][3])
                    : "r"(a[mf][0]), "r"(a[mf][1]), "r"(a[mf][2]), "r"(a[mf][3]),
                      "r"(b[nf][0]), "r"(b[nf][1]));
            }
    }
}

// ------------------------------------------------------------------
// full-K (K=128) GEMM accumulate: single tile, single sync.
// smem: Xs [128][136] + Ws [128][136] = 69632 B, stride 68 words.
// ------------------------------------------------------------------
template<typename InT>
__device__ __forceinline__
void gemm_accum_full(const InT* __restrict__ X, const float* __restrict__ W,
                     int M, int row0, int wBase, char* smemc, float c[4][4][4]) {
    constexpr int K = 128;
    constexpr int KP = 136;
    __half* Xs = reinterpret_cast<__half*>(smemc);
    __half* Ws = Xs + 128 * KP;

    const int tid = threadIdx.x;
    const int lane = tid & 31;
    const int wid = tid >> 5;
    const int warpM = wid >> 2, warpN = wid & 3;
    const int g = lane >> 2, qc = lane & 3;

#pragma unroll
    for (int mf = 0; mf < 4; ++mf)
#pragma unroll
        for (int nf = 0; nf < 4; ++nf)
#pragma unroll
            for (int q = 0; q < 4; ++q) c[mf][nf][q] = 0.f;

    // X tile: 128 rows x 32 4-elem chunks
    for (int i = tid; i < 128 * 32; i += 256) {
        int r = i >> 5;
        int k4 = (i & 31) << 2;
        int gr = row0 + r;
        if constexpr (sizeof(InT) == 4) {
            float4 v = make_float4(0.f, 0.f, 0.f, 0.f);
            if (gr < M) v = *reinterpret_cast<const float4*>(X + (size_t)gr * K + k4);
            __half2 h0 = __floats2half2_rn(v.x, v.y);
            __half2 h1 = __floats2half2_rn(v.z, v.w);
            uint2 u = make_uint2(*reinterpret_cast<uint32_t*>(&h0),
                                 *reinterpret_cast<uint32_t*>(&h1));
            *reinterpret_cast<uint2*>(Xs + r * KP + k4) = u;
        } else {
            uint2 u = make_uint2(0u, 0u);
            if (gr < M) u = *reinterpret_cast<const uint2*>(X + (size_t)gr * K + k4);
            *reinterpret_cast<uint2*>(Xs + r * KP + k4) = u;
        }
    }
    // W tile: 128 rows x 32 chunks
    for (int i = tid; i < 128 * 32; i += 256) {
        int r = i >> 5;
        int k4 = (i & 31) << 2;
        float4 v = *reinterpret_cast<const float4*>(W + (size_t)(wBase + r) * K + k4);
        __half2 h0 = __floats2half2_rn(v.x, v.y);
        __half2 h1 = __floats2half2_rn(v.z, v.w);
        uint2 u = make_uint2(*reinterpret_cast<uint32_t*>(&h0),
                             *reinterpret_cast<uint32_t*>(&h1));
        *reinterpret_cast<uint2*>(Ws + r * KP + k4) = u;
    }
    __syncthreads();

    mma_sweep<8>(Xs, Ws, KP / 2, c, warpM, warpN, g, qc);
}

template<typename InT, typename OutT>
__global__ __launch_bounds__(256, 2)
void mma_gemm(const InT* __restrict__ X, const float* __restrict__ W,
              const float* __restrict__ Dadd, OutT* __restrict__ C,
              int M, int ldc) {
    extern __shared__ char smemc[];
    float c[4][4][4];
    const int row0 = blockIdx.x * 128;
    const int nBase = blockIdx.y * 128;
    gemm_accum_full<InT>(X, W, M, row0, nBase, smemc, c);

    const int lane = threadIdx.x & 31;
    const int wid = threadIdx.x >> 5;
    const int warpM = wid >> 2, warpN = wid & 3;
    const int g = lane >> 2, qc = lane & 3;
#pragma unroll
    for (int mf = 0; mf < 4; ++mf) {
#pragma unroll
        for (int nf = 0; nf < 4; ++nf) {
            int col = nBase + warpN * 32 + nf * 8 + qc * 2;
#pragma unroll
            for (int half = 0; half < 2; ++half) {
                int r = row0 + warpM * 64 + mf * 16 + g + half * 8;
                if (r >= M) continue;
                float ox = c[mf][nf][half * 2 + 0];
                float oy = c[mf][nf][half * 2 + 1];
                if constexpr (sizeof(OutT) == 4) {
                    if (Dadd) {
                        float2 d = *reinterpret_cast<const float2*>(
                            Dadd + (size_t)r * ldc + col);
                        ox += d.x; oy += d.y;
                    }
                    *reinterpret_cast<float2*>(
                        reinterpret_cast<float*>(C) + (size_t)r * ldc + col) =
                        make_float2(ox, oy);
                } else {
                    __half2 h = __floats2half2_rn(ox, oy);
                    *reinterpret_cast<__half2*>(
                        reinterpret_cast<__half*>(C) + (size_t)r * ldc + col) = h;
                }
            }
        }
    }
}

// merged vertex GEMM: y in 0..3 -> [Vsrc core, Vsrc gate, Vdst core, Vdst gate]
__global__ __launch_bounds__(256, 2)
void mma_gemm_vertex(const float* __restrict__ X, const float* __restrict__ W,
                     __half* __restrict__ C0, __half* __restrict__ C1, int M) {
    extern __shared__ char smemc[];
    float c[4][4][4];
    const int y = blockIdx.y;
    const int row0 = blockIdx.x * 128;
    __half* C = (y < 2) ? C0 : C1;
    const int colBase = (y & 1) * 128;
    gemm_accum_full<float>(X, W, M, row0, y * 128, smemc, c);

    const int lane = threadIdx.x & 31;
    const int wid = threadIdx.x >> 5;
    const int warpM = wid >> 2, warpN = wid & 3;
    const int g = lane >> 2, qc = lane & 3;
#pragma unroll
    for (int mf = 0; mf < 4; ++mf) {
#pragma unroll
        for (int nf = 0; nf < 4; ++nf) {
            int col = colBase + warpN * 32 + nf * 8 + qc * 2;
#pragma unroll
            for (int half = 0; half < 2; ++half) {
                int r = row0 + warpM * 64 + mf * 16 + g + half * 8;
                if (r >= M) continue;
                __half2 h = __floats2half2_rn(c[mf][nf][half * 2 + 0],
                                              c[mf][nf][half * 2 + 1]);
                *reinterpret_cast<__half2*>(C + (size_t)r * 256 + col) = h;
            }
        }
    }
}

// ------------------------------------------------------------------
// Fused angle GEMM over FULL N=256 + gather-add + BN stats. (champion, unchanged)
// smem: Xs 18432 + Ws 18432 + Cs 67584 = 104448 B
// ------------------------------------------------------------------
__global__ __launch_bounds__(256, 2)
void angle_fuse(const float* __restrict__ X, const float* __restrict__ W,
                const int* __restrict__ kx, const int* __restrict__ jx,
                const int* __restrict__ ix, int T) {
    extern __shared__ char smemc[];
    __half* Xs = reinterpret_cast<__half*>(smemc);       // [128][72]
    __half* Ws = Xs + 128 * 72;                          // [128][72]
    __half* Cs = Ws + 128 * 72;                          // [128][264]
    __shared__ float s_sum[256];
    __shared__ float s_ssq[256];

    const int tid = threadIdx.x;
    const int lane = tid & 31;
    const int wid = tid >> 5;
    const int warpM = wid >> 2, warpN = wid & 3;
    const int g = lane >> 2, qc = lane & 3;
    const int row0 = blockIdx.x * 128;

    s_sum[tid] = 0.f; s_ssq[tid] = 0.f;

    for (int i = tid; i < 128 * 16; i += 256) {
        int r = i >> 4;
        int k4 = (i & 15) << 2;
        int gr = row0 + r;
        float4 v = make_float4(0.f, 0.f, 0.f, 0.f);
        if (gr < T) v = *reinterpret_cast<const float4*>(X + (size_t)gr * 64 + k4);
        __half2 h0 = __floats2half2_rn(v.x, v.y);
        __half2 h1 = __floats2half2_rn(v.z, v.w);
        uint2 u = make_uint2(*reinterpret_cast<uint32_t*>(&h0),
                             *reinterpret_cast<uint32_t*>(&h1));
        *reinterpret_cast<uint2*>(Xs + r * 72 + k4) = u;
    }

    float c[4][4][4];
#pragma unroll
    for (int pass = 0; pass < 2; ++pass) {
        for (int i = tid; i < 128 * 16; i += 256) {
            int r = i >> 4;
            int k4 = (i & 15) << 2;
            float4 v = *reinterpret_cast<const float4*>(
                W + (size_t)(pass * 128 + r) * 64 + k4);
            __half2 h0 = __floats2half2_rn(v.x, v.y);
            __half2 h1 = __floats2half2_rn(v.z, v.w);
            uint2 u = make_uint2(*reinterpret_cast<uint32_t*>(&h0),
                                 *reinterpret_cast<uint32_t*>(&h1));
            *reinterpret_cast<uint2*>(Ws + r * 72 + k4) = u;
        }
        __syncthreads();

#pragma unroll
        for (int mf = 0; mf < 4; ++mf)
#pragma unroll
            for (int nf = 0; nf < 4; ++nf)
#pragma unroll
                for (int q = 0; q < 4; ++q) c[mf][nf][q] = 0.f;
        mma_sweep<4>(Xs, Ws, 36, c, warpM, warpN, g, qc);

#pragma unroll
        for (int mf = 0; mf < 4; ++mf) {
#pragma unroll
            for (int nf = 0; nf < 4; ++nf) {
                int col = pass * 128 + warpN * 32 + nf * 8 + qc * 2;
#pragma unroll
                for (int half = 0; half < 2; ++half) {
                    int r = warpM * 64 + mf * 16 + g + half * 8;
                    __half2 h = __floats2half2_rn(c[mf][nf][half * 2 + 0],
                                                  c[mf][nf][half * 2 + 1]);
                    *reinterpret_cast<__half2*>(Cs + r * 264 + col) = h;
                }
            }
        }
        __syncthreads();
    }

    const int c4 = lane * 4;
    float4 sumC = make_float4(0, 0, 0, 0), ssqC = make_float4(0, 0, 0, 0);
    float4 sumG = make_float4(0, 0, 0, 0), ssqG = make_float4(0, 0, 0, 0);

    for (int rr = 0; rr < 16; rr += 2) {
        int r0 = wid * 16 + rr;
        int t0 = row0 + r0;
        int t1 = t0 + 1;
        bool v0 = t0 < T, v1 = t1 < T;

        float4 aC0, aG0, sC0, sG0, eC0, eG0, dC0, dG0;
        float4 aC1, aG1, sC1, sG1, eC1, eG1, dC1, dG1;
        if (v0) {
            int j = jx[t0], k = kx[t0], i = ix[t0];
            aC0 = ldh4(Cs + r0 * 264 + c4);
            aG0 = ldh4(Cs + r0 * 264 + 128 + c4);
            sC0 = ldh4(g_Vsrc + (size_t)j * 256 + c4);
            sG0 = ldh4(g_Vsrc + (size_t)j * 256 + 128 + c4);
            eC0 = ldh4(g_Ep + (size_t)k * 256 + c4);
            eG0 = ldh4(g_Ep + (size_t)k * 256 + 128 + c4);
            dC0 = ldh4(g_Vdst + (size_t)i * 256 + c4);
            dG0 = ldh4(g_Vdst + (size_t)i * 256 + 128 + c4);
        }
        if (v1) {
            int j = jx[t1], k = kx[t1], i = ix[t1];
            aC1 = ldh4(Cs + (r0 + 1) * 264 + c4);
            aG1 = ldh4(Cs + (r0 + 1) * 264 + 128 + c4);
            sC1 = ldh4(g_Vsrc + (size_t)j * 256 + c4);
            sG1 = ldh4(g_Vsrc + (size_t)j * 256 + 128 + c4);
            eC1 = ldh4(g_Ep + (size_t)k * 256 + c4);
            eG1 = ldh4(g_Ep + (size_t)k * 256 + 128 + c4);
            dC1 = ldh4(g_Vdst + (size_t)i * 256 + c4);
            dG1 = ldh4(g_Vdst + (size_t)i * 256 + 128 + c4);
        }

#pragma unroll
        for (int u = 0; u < 2; ++u) {
            bool v = u ? v1 : v0;
            if (!v) continue;
            int t = u ? t1 : t0;
            float4 oc = u ? f4add(f4add(aC1, sC1), f4add(eC1, dC1))
                          : f4add(f4add(aC0, sC0), f4add(eC0, dC0));
            float4 og = u ? f4add(f4add(aG1, sG1), f4add(eG1, dG1))
                          : f4add(f4add(aG0, sG0), f4add(eG0, dG0));
            __half2 hc0 = __floats2half2_rn(oc.x, oc.y);
            __half2 hc1 = __floats2half2_rn(oc.z, oc.w);
            __half2 hg0 = __floats2half2_rn(og.x, og.y);
            __half2 hg1 = __floats2half2_rn(og.z, og.w);
            uint2 uc = make_uint2(*reinterpret_cast<uint32_t*>(&hc0),
                                  *reinterpret_cast<uint32_t*>(&hc1));
            uint2 ug = make_uint2(*reinterpret_cast<uint32_t*>(&hg0),
                                  *reinterpret_cast<uint32_t*>(&hg1));
            *reinterpret_cast<uint2*>(g_A + (size_t)t * 256 + c4) = uc;
            *reinterpret_cast<uint2*>(g_A + (size_t)t * 256 + 128 + c4) = ug;
            float2 fc0 = __half22float2(hc0), fc1 = __half22float2(hc1);
            float2 fg0 = __half22float2(hg0), fg1 = __half22float2(hg1);
            sumC.x += fc0.x; sumC.y += fc0.y; sumC.z += fc1.x; sumC.w += fc1.y;
            ssqC.x += fc0.x * fc0.x; ssqC.y += fc0.y * fc0.y;
            ssqC.z += fc1.x * fc1.x; ssqC.w += fc1.y * fc1.y;
            sumG.x += fg0.x; sumG.y += fg0.y; sumG.z += fg1.x; sumG.w += fg1.y;
            ssqG.x += fg0.x * fg0.x; ssqG.y += fg0.y * fg0.y;
            ssqG.z += fg1.x * fg1.x; ssqG.w += fg1.y * fg1.y;
        }
    }

    atomicAdd(&s_sum[c4 + 0], sumC.x); atomicAdd(&s_sum[c4 + 1], sumC.y);
    atomicAdd(&s_sum[c4 + 2], sumC.z); atomicAdd(&s_sum[c4 + 3], sumC.w);
    atomicAdd(&s_ssq[c4 + 0], ssqC.x); atomicAdd(&s_ssq[c4 + 1], ssqC.y);
    atomicAdd(&s_ssq[c4 + 2], ssqC.z); atomicAdd(&s_ssq[c4 + 3], ssqC.w);
    atomicAdd(&s_sum[128 + c4 + 0], sumG.x); atomicAdd(&s_sum[128 + c4 + 1], sumG.y);
    atomicAdd(&s_sum[128 + c4 + 2], sumG.z); atomicAdd(&s_sum[128 + c4 + 3], sumG.w);
    atomicAdd(&s_ssq[128 + c4 + 0], ssqG.x); atomicAdd(&s_ssq[128 + c4 + 1], ssqG.y);
    atomicAdd(&s_ssq[128 + c4 + 2], ssqG.z); atomicAdd(&s_ssq[128 + c4 + 3], ssqG.w);
    __syncthreads();
    if (tid < 128) {
        atomicAdd(&g_stats[tid], s_sum[tid]);
        atomicAdd(&g_stats[128 + tid], s_ssq[tid]);
    } else {
        int t = tid - 128;
        atomicAdd(&g_stats[256 + t], s_sum[tid]);
        atomicAdd(&g_stats[384 + t], s_ssq[tid]);
    }
}

// ------------------------------------------------------------------
__global__ void finalize_stats(const float* __restrict__ gamC, const float* __restrict__ betC,
                               const float* __restrict__ gamG, const float* __restrict__ betG,
                               float invT) {
    int c = threadIdx.x;  // 128 threads
    float m = g_stats[c] * invT;
    float v = g_stats[128 + c] * invT - m * m;
    float a = rsqrtf(v + BN_EPS) * gamC[c];
    g_scale[c] = a;
    g_scale[128 + c] = betC[c] - m * a;

    m = g_stats[256 + c] * invT;
    v = g_stats[384 + c] * invT - m * m;
    a = rsqrtf(v + BN_EPS) * gamG[c];
    g_scale[256 + c] = a;
    g_scale[384 + c] = betG[c] - m * a;
}

// ------------------------------------------------------------------
__device__ __forceinline__ float sigf(float x) { return 1.0f / (1.0f + __expf(-x)); }

// champion version: uint2 loads per half, fp16x2 atomics, x2 unrolled.
__global__ void pass_scatter(const int* __restrict__ kx, int T) {
    const int lane = threadIdx.x & 31;
    int warp = (blockIdx.x * blockDim.x + threadIdx.x) >> 5;
    const int nw = (gridDim.x * blockDim.x) >> 5;
    const int c4 = lane * 4;

    const float4 ac = reinterpret_cast<const float4*>(g_scale)[lane];
    const float4 bc = reinterpret_cast<const float4*>(g_scale + 128)[lane];
    const float4 ag = reinterpret_cast<const float4*>(g_scale + 256)[lane];
    const float4 bg = reinterpret_cast<const float4*>(g_scale + 384)[lane];

    for (int t0 = warp * 2; t0 < T; t0 += nw * 2) {
        int t1 = t0 + 1;
        bool h1 = t1 < T;
        int k0 = kx[t0];
        int k1 = h1 ? kx[t1] : k0;

        const __half* A0 = g_A + (size_t)t0 * 256;
        const __half* A1 = g_A + (size_t)t1 * 256;
        float4 c0 = ldh4(A0 + c4), g0 = ldh4(A0 + 128 + c4);
        float4 c1, g1;
        if (h1) { c1 = ldh4(A1 + c4); g1 = ldh4(A1 + 128 + c4); }

        {
            float cnx = c0.x * ac.x + bc.x, cny = c0.y * ac.y + bc.y;
            float cnz = c0.z * ac.z + bc.z, cnw = c0.w * ac.w + bc.w;
            float gnx = g0.x * ag.x + bg.x, gny = g0.y * ag.y + bg.y;
            float gnz = g0.z * ag.z + bg.z, gnw = g0.w * ag.w + bg.w;
            __half2* dst = reinterpret_cast<__half2*>(g_seg + (size_t)k0 * 128 + c4);
            atomicAdd(dst, __floats2half2_rn(cnx * sigf(cnx) * sigf(gnx),
                                             cny * sigf(cny) * sigf(gny)));
            atomicAdd(dst + 1, __floats2half2_rn(cnz * sigf(cnz) * sigf(gnz),
                                                 cnw * sigf(cnw) * sigf(gnw)));
        }
        if (h1) {
            float cnx = c1.x * ac.x + bc.x, cny = c1.y * ac.y + bc.y;
            float cnz = c1.z * ac.z + bc.z, cnw = c1.w * ac.w + bc.w;
            float gnx = g1.x * ag.x + bg.x, gny = g1.y * ag.y + bg.y;
            float gnz = g1.z * ag.z + bg.z, gnw = g1.w * ag.w + bg.w;
            __half2* dst = reinterpret_cast<__half2*>(g_seg + (size_t)k1 * 128 + c4);
            atomicAdd(dst, __floats2half2_rn(cnx * sigf(cnx) * sigf(gnx),
                                             cny * sigf(cny) * sigf(gny)));
            atomicAdd(dst + 1, __floats2half2_rn(cnz * sigf(cnz) * sigf(gnz),
                                                 cnw * sigf(cnw) * sigf(gnw)));
        }
    }
}

// ------------------------------------------------------------------
extern "C" void kernel_launch(void* const* d_in, const int* in_sizes, int n_in,
                              void* d_out, int out_size) {
    const float* vertex = (const float*)d_in[0];
    const float* edge   = (const float*)d_in[1];
    const float* angle  = (const float*)d_in[2];
    const int* kx = (const int*)d_in[4];
    const int* jx = (const int*)d_in[5];
    const int* ix = (const int*)d_in[6];
    const float* w_cs = (const float*)d_in[7];
    const float* w_cd = (const float*)d_in[8];
    const float* w_cb = (const float*)d_in[9];
    const float* w_ca = (const float*)d_in[10];
    const float* w_gs = (const float*)d_in[11];
    const float* w_gd = (const float*)d_in[12];
    const float* w_gb = (const float*)d_in[13];
    const float* w_ga = (const float*)d_in[14];
    const float* bcg = (const float*)d_in[15];
    const float* bcb = (const float*)d_in[16];
    const float* bgg = (const float*)d_in[17];
    const float* bgb = (const float*)d_in[18];
    const float* w_out = (const float*)d_in[19];

    const int N = in_sizes[0] / 128;
    const int E = in_sizes[1] / 128;
    const int T = in_sizes[2] / 64;

    __half *pVsrc, *pVdst, *pEp, *pSeg;
    float *pWv, *pWeb, *pWan;
    cudaGetSymbolAddress((void**)&pVsrc, g_Vsrc);
    cudaGetSymbolAddress((void**)&pVdst, g_Vdst);
    cudaGetSymbolAddress((void**)&pEp, g_Ep);
    cudaGetSymbolAddress((void**)&pSeg, g_seg);
    cudaGetSymbolAddress((void**)&pWv, g_Wv);
    cudaGetSymbolAddress((void**)&pWeb, g_Web);
    cudaGetSymbolAddress((void**)&pWan, g_Wan);

    const size_t smem_gemm = 2 * 128 * 136 * sizeof(__half);               // 69632
    const size_t smem_fuse = (2 * 128 * 72 + 128 * 264) * sizeof(__half);  // 104448
    cudaFuncSetAttribute(mma_gemm<float, __half>,
                         cudaFuncAttributeMaxDynamicSharedMemorySize, (int)smem_gemm);
    cudaFuncSetAttribute(mma_gemm<__half, float>,
                         cudaFuncAttributeMaxDynamicSharedMemorySize, (int)smem_gemm);
    cudaFuncSetAttribute(mma_gemm_vertex,
                         cudaFuncAttributeMaxDynamicSharedMemorySize, (int)smem_gemm);
    cudaFuncSetAttribute(angle_fuse,
                         cudaFuncAttributeMaxDynamicSharedMemorySize, (int)smem_fuse);

    zero_kernel<<<2048, 256>>>(E);
    pack_all<<<96, 256>>>(w_cs, w_gs, w_cd, w_gd, w_cb, w_gb, w_ca, w_ga);

    const int gN = (N + 127) / 128;
    const int gE = (E + 127) / 128;
    const int gT = (T + 127) / 128;

    // vertex: single launch, 4 output tiles (Vsrc core|gate, Vdst core|gate)
    mma_gemm_vertex<<<dim3(gN, 4), 256, smem_gemm>>>(vertex, pWv, pVsrc, pVdst, N);
    mma_gemm<float, __half><<<dim3(gE, 2), 256, smem_gemm>>>(
        edge, pWeb, nullptr, pEp, E, 256);

    // fused: angle GEMM (full N=256) + gather-add + BN stats
    angle_fuse<<<gT, 256, smem_fuse>>>(angle, pWan, kx, jx, ix, T);

    finalize_stats<<<1, 128>>>(bcg, bcb, bgg, bgb, 1.0f / (float)T);

    // activation + segment scatter (fp16x2 atomics), x2 unrolled
    pass_scatter<<<1184, 256>>>(kx, T);

    // new_bond = seg(fp16) @ w_out.T + edge_feat  (fp32 output)
    mma_gemm<__half, float><<<dim3(gE, 1), 256, smem_gemm>>>(
        pSeg, w_out, edge, (float*)d_out, E, 128);
}

// round 16
// speedup vs baseline: 1.2142x; 1.2142x over previous
#include <cuda_runtime.h>
#include <cuda_fp16.h>
#include <cstdint>

#define BN_EPS 1e-5f
#define MAXN 100000
#define MAXE 400000
#define MAXT 1000000

// ---- scratch (allocation-free, static device globals) ----
__device__ __half g_Vsrc[(size_t)MAXN * 256];  // [N,256] = [core_src | gate_src]
__device__ __half g_Vdst[(size_t)MAXN * 256];  // [N,256] = [core_dst | gate_dst]
__device__ __half g_Ep  [(size_t)MAXE * 256];  // [E,256] = [core_bond | gate_bond]
__device__ __half g_A   [(size_t)MAXT * 256];  // [T,256] fused core|gate (pre-BN)
__device__ __half g_seg [(size_t)MAXE * 128];  // segment sums (fp16x2 atomics)
__device__ float  g_stats[512];                // sumC | ssqC | sumG | ssqG
__device__ float  g_scale[512];                // aC | bC | aG | bG
__device__ float  g_Wv [512 * 128];            // [w_core_src; w_gate_src; w_core_dst; w_gate_dst]
__device__ float  g_Web[256 * 128];            // [w_core_bond ; w_gate_bond]
__device__ float  g_Wan[256 * 64];             // [w_core_angle ; w_gate_angle]

// ------------------------------------------------------------------
// merged preamble: zero seg buffer + stats, pack all weight pairs.
// ------------------------------------------------------------------
__global__ void preamble(const float* __restrict__ cs, const float* __restrict__ gs,
                         const float* __restrict__ cd, const float* __restrict__ gd,
                         const float* __restrict__ cb, const float* __restrict__ gb,
                         const float* __restrict__ ca, const float* __restrict__ ga,
                         int E) {
    size_t n16 = (size_t)E * 16;   // E*128 halves / 8 per uint4
    size_t i = (size_t)blockIdx.x * blockDim.x + threadIdx.x;
    size_t st = (size_t)gridDim.x * blockDim.x;
    uint4 z = make_uint4(0, 0, 0, 0);
    uint4* p = reinterpret_cast<uint4*>(g_seg);
    for (size_t k = i; k < n16; k += st) p[k] = z;

    int ii = (int)i;
    if (ii < 512) g_stats[ii] = 0.f;
    if (ii < 16384) {
        g_Wv[ii] = cs[ii];           g_Wv[16384 + ii] = gs[ii];
        g_Wv[32768 + ii] = cd[ii];   g_Wv[49152 + ii] = gd[ii];
        g_Web[ii] = cb[ii];          g_Web[16384 + ii] = gb[ii];
    }
    if (ii < 8192) {
        g_Wan[ii] = ca[ii];          g_Wan[8192 + ii] = ga[ii];
    }
}

// ---- fp16 helpers ----
__device__ __forceinline__ float4 ldh4(const __half* p) {
    uint2 u = *reinterpret_cast<const uint2*>(p);
    __half2 h0 = *reinterpret_cast<__half2*>(&u.x);
    __half2 h1 = *reinterpret_cast<__half2*>(&u.y);
    float2 f0 = __half22float2(h0);
    float2 f1 = __half22float2(h1);
    return make_float4(f0.x, f0.y, f1.x, f1.y);
}
__device__ __forceinline__ float4 f4add(float4 a, float4 b) {
    return make_float4(a.x + b.x, a.y + b.y, a.z + b.z, a.w + b.w);
}

// ------------------------------------------------------------------
// 128x128x64 fp16 MMA sweep; word stride 36 (72-half rows)
// ------------------------------------------------------------------
__device__ __forceinline__
void mma64(const __half* Xs, const __half* Ws, float c[4][4][4],
           int warpM, int warpN, int g, int qc) {
    const uint32_t* Xu = reinterpret_cast<const uint32_t*>(Xs);
    const uint32_t* Wu = reinterpret_cast<const uint32_t*>(Ws);
#pragma unroll
    for (int k0 = 0; k0 < 64; k0 += 16) {
        const int kw = k0 >> 1;
        uint32_t a[4][4], b[4][2];
#pragma unroll
        for (int mf = 0; mf < 4; ++mf) {
            int r = warpM * 64 + mf * 16 + g;
            a[mf][0] = Xu[r * 36 + kw + qc];
            a[mf][1] = Xu[(r + 8) * 36 + kw + qc];
            a[mf][2] = Xu[r * 36 + kw + 4 + qc];
            a[mf][3] = Xu[(r + 8) * 36 + kw + 4 + qc];
        }
#pragma unroll
        for (int nf = 0; nf < 4; ++nf) {
            int n = warpN * 32 + nf * 8 + g;
            b[nf][0] = Wu[n * 36 + kw + qc];
            b[nf][1] = Wu[n * 36 + kw + 4 + qc];
        }
#pragma unroll
        for (int mf = 0; mf < 4; ++mf)
#pragma unroll
            for (int nf = 0; nf < 4; ++nf) {
                asm volatile(
                    "mma.sync.aligned.m16n8k16.row.col.f32.f16.f16.f32 "
                    "{%0,%1,%2,%3}, {%4,%5,%6,%7}, {%8,%9}, {%0,%1,%2,%3};"
                    : "+f"(c[mf][nf][0]), "+f"(c[mf][nf][1]),
                      "+f"(c[mf][nf][2]), "+f"(c[mf][nf][3])
                    : "r"(a[mf][0]), "r"(a[mf][1]), "r"(a[mf][2]), "r"(a[mf][3]),
                      "r"(b[nf][0]), "r"(b[nf][1]));
            }
    }
}

// ------------------------------------------------------------------
// generic GEMM accumulate (input fp32 or fp16), 128x128 tile, BK=64 loop
// ------------------------------------------------------------------
template<int K, typename InT>
__device__ __forceinline__
void gemm_accum(const InT* __restrict__ X, const float* __restrict__ W,
                int M, int row0, int wBase, char* smemc, float c[4][4][4]) {
    constexpr int BK = 64;
    constexpr int KP = 72;
    __half* Xs = reinterpret_cast<__half*>(smemc);
    __half* Ws = Xs + 128 * KP;

    const int tid = threadIdx.x;
    const int lane = tid & 31;
    const int wid = tid >> 5;
    const int warpM = wid >> 2, warpN = wid & 3;
    const int g = lane >> 2, qc = lane & 3;

#pragma unroll
    for (int mf = 0; mf < 4; ++mf)
#pragma unroll
        for (int nf = 0; nf < 4; ++nf)
#pragma unroll
            for (int q = 0; q < 4; ++q) c[mf][nf][q] = 0.f;

    for (int kt = 0; kt < K; kt += BK) {
        for (int i = tid; i < 128 * (BK / 4); i += 256) {
            int r = i >> 4;
            int k4 = (i & 15) << 2;
            int gr = row0 + r;
            if constexpr (sizeof(InT) == 4) {
                float4 v = make_float4(0.f, 0.f, 0.f, 0.f);
                if (gr < M)
                    v = *reinterpret_cast<const float4*>(X + (size_t)gr * K + kt + k4);
                __half2 h0 = __floats2half2_rn(v.x, v.y);
                __half2 h1 = __floats2half2_rn(v.z, v.w);
                uint2 u = make_uint2(*reinterpret_cast<uint32_t*>(&h0),
                                     *reinterpret_cast<uint32_t*>(&h1));
                *reinterpret_cast<uint2*>(Xs + r * KP + k4) = u;
            } else {
                uint2 u = make_uint2(0u, 0u);
                if (gr < M)
                    u = *reinterpret_cast<const uint2*>(X + (size_t)gr * K + kt + k4);
                *reinterpret_cast<uint2*>(Xs + r * KP + k4) = u;
            }
        }
        for (int i = tid; i < 128 * (BK / 4); i += 256) {
            int r = i >> 4;
            int k4 = (i & 15) << 2;
            float4 v = *reinterpret_cast<const float4*>(W + (size_t)(wBase + r) * K + kt + k4);
            __half2 h0 = __floats2half2_rn(v.x, v.y);
            __half2 h1 = __floats2half2_rn(v.z, v.w);
            uint2 u = make_uint2(*reinterpret_cast<uint32_t*>(&h0),
                                 *reinterpret_cast<uint32_t*>(&h1));
            *reinterpret_cast<uint2*>(Ws + r * KP + k4) = u;
        }
        __syncthreads();
        mma64(Xs, Ws, c, warpM, warpN, g, qc);
        __syncthreads();
    }
}

template<int K, typename InT, typename OutT>
__global__ __launch_bounds__(256, 2)
void mma_gemm(const InT* __restrict__ X, const float* __restrict__ W,
              const float* __restrict__ Dadd, OutT* __restrict__ C,
              int M, int ldc) {
    extern __shared__ char smemc[];
    float c[4][4][4];
    const int row0 = blockIdx.x * 128;
    const int nBase = blockIdx.y * 128;
    gemm_accum<K, InT>(X, W, M, row0, nBase, smemc, c);

    const int lane = threadIdx.x & 31;
    const int wid = threadIdx.x >> 5;
    const int warpM = wid >> 2, warpN = wid & 3;
    const int g = lane >> 2, qc = lane & 3;
#pragma unroll
    for (int mf = 0; mf < 4; ++mf) {
#pragma unroll
        for (int nf = 0; nf < 4; ++nf) {
            int col = nBase + warpN * 32 + nf * 8 + qc * 2;
#pragma unroll
            for (int half = 0; half < 2; ++half) {
                int r = row0 + warpM * 64 + mf * 16 + g + half * 8;
                if (r >= M) continue;
                float ox = c[mf][nf][half * 2 + 0];
                float oy = c[mf][nf][half * 2 + 1];
                if constexpr (sizeof(OutT) == 4) {
                    if (Dadd) {
                        float2 d = *reinterpret_cast<const float2*>(
                            Dadd + (size_t)r * ldc + col);
                        ox += d.x; oy += d.y;
                    }
                    *reinterpret_cast<float2*>(
                        reinterpret_cast<float*>(C) + (size_t)r * ldc + col) =
                        make_float2(ox, oy);
                } else {
                    __half2 h = __floats2half2_rn(ox, oy);
                    *reinterpret_cast<__half2*>(
                        reinterpret_cast<__half*>(C) + (size_t)r * ldc + col) = h;
                }
            }
        }
    }
}

// merged vertex GEMM: y in 0..3 -> [Vsrc core, Vsrc gate, Vdst core, Vdst gate]
__global__ __launch_bounds__(256, 2)
void mma_gemm_vertex(const float* __restrict__ X, const float* __restrict__ W,
                     __half* __restrict__ C0, __half* __restrict__ C1, int M) {
    extern __shared__ char smemc[];
    float c[4][4][4];
    const int y = blockIdx.y;
    const int row0 = blockIdx.x * 128;
    __half* C = (y < 2) ? C0 : C1;
    const int colBase = (y & 1) * 128;
    gemm_accum<128, float>(X, W, M, row0, y * 128, smemc, c);

    const int lane = threadIdx.x & 31;
    const int wid = threadIdx.x >> 5;
    const int warpM = wid >> 2, warpN = wid & 3;
    const int g = lane >> 2, qc = lane & 3;
#pragma unroll
    for (int mf = 0; mf < 4; ++mf) {
#pragma unroll
        for (int nf = 0; nf < 4; ++nf) {
            int col = colBase + warpN * 32 + nf * 8 + qc * 2;
#pragma unroll
            for (int half = 0; half < 2; ++half) {
                int r = row0 + warpM * 64 + mf * 16 + g + half * 8;
                if (r >= M) continue;
                __half2 h = __floats2half2_rn(c[mf][nf][half * 2 + 0],
                                              c[mf][nf][half * 2 + 1]);
                *reinterpret_cast<__half2*>(C + (size_t)r * 256 + col) = h;
            }
        }
    }
}

// ------------------------------------------------------------------
// Fused angle GEMM over FULL N=256 + gather-add + BN stats.
// smem: Xs 18432 + Ws 18432 + Cs 67584 = 104448 B
// ------------------------------------------------------------------
__global__ __launch_bounds__(256, 2)
void angle_fuse(const float* __restrict__ X, const float* __restrict__ W,
                const int* __restrict__ kx, const int* __restrict__ jx,
                const int* __restrict__ ix, int T) {
    extern __shared__ char smemc[];
    __half* Xs = reinterpret_cast<__half*>(smemc);       // [128][72]
    __half* Ws = Xs + 128 * 72;                          // [128][72]
    __half* Cs = Ws + 128 * 72;                          // [128][264]
    __shared__ float s_sum[256];
    __shared__ float s_ssq[256];

    const int tid = threadIdx.x;
    const int lane = tid & 31;
    const int wid = tid >> 5;
    const int warpM = wid >> 2, warpN = wid & 3;
    const int g = lane >> 2, qc = lane & 3;
    const int row0 = blockIdx.x * 128;

    s_sum[tid] = 0.f; s_ssq[tid] = 0.f;

    // ---- load Xs (K=64) ----
    for (int i = tid; i < 128 * 16; i += 256) {
        int r = i >> 4;
        int k4 = (i & 15) << 2;
        int gr = row0 + r;
        float4 v = make_float4(0.f, 0.f, 0.f, 0.f);
        if (gr < T) v = *reinterpret_cast<const float4*>(X + (size_t)gr * 64 + k4);
        __half2 h0 = __floats2half2_rn(v.x, v.y);
        __half2 h1 = __floats2half2_rn(v.z, v.w);
        uint2 u = make_uint2(*reinterpret_cast<uint32_t*>(&h0),
                             *reinterpret_cast<uint32_t*>(&h1));
        *reinterpret_cast<uint2*>(Xs + r * 72 + k4) = u;
    }

    float c[4][4][4];
#pragma unroll
    for (int pass = 0; pass < 2; ++pass) {
        for (int i = tid; i < 128 * 16; i += 256) {
            int r = i >> 4;
            int k4 = (i & 15) << 2;
            float4 v = *reinterpret_cast<const float4*>(
                W + (size_t)(pass * 128 + r) * 64 + k4);
            __half2 h0 = __floats2half2_rn(v.x, v.y);
            __half2 h1 = __floats2half2_rn(v.z, v.w);
            uint2 u = make_uint2(*reinterpret_cast<uint32_t*>(&h0),
                                 *reinterpret_cast<uint32_t*>(&h1));
            *reinterpret_cast<uint2*>(Ws + r * 72 + k4) = u;
        }
        __syncthreads();

#pragma unroll
        for (int mf = 0; mf < 4; ++mf)
#pragma unroll
            for (int nf = 0; nf < 4; ++nf)
#pragma unroll
                for (int q = 0; q < 4; ++q) c[mf][nf][q] = 0.f;
        mma64(Xs, Ws, c, warpM, warpN, g, qc);

#pragma unroll
        for (int mf = 0; mf < 4; ++mf) {
#pragma unroll
            for (int nf = 0; nf < 4; ++nf) {
                int col = pass * 128 + warpN * 32 + nf * 8 + qc * 2;
#pragma unroll
                for (int half = 0; half < 2; ++half) {
                    int r = warpM * 64 + mf * 16 + g + half * 8;
                    __half2 h = __floats2half2_rn(c[mf][nf][half * 2 + 0],
                                                  c[mf][nf][half * 2 + 1]);
                    *reinterpret_cast<__half2*>(Cs + r * 264 + col) = h;
                }
            }
        }
        __syncthreads();
    }

    // ---- phase 3: warp-per-row gather-add (float4/uint2 granularity) ----
    const int c4 = lane * 4;
    float4 sumC = make_float4(0, 0, 0, 0), ssqC = make_float4(0, 0, 0, 0);
    float4 sumG = make_float4(0, 0, 0, 0), ssqG = make_float4(0, 0, 0, 0);

    for (int rr = 0; rr < 16; rr += 2) {
        int r0 = wid * 16 + rr;
        int t0 = row0 + r0;
        int t1 = t0 + 1;
        bool v0 = t0 < T, v1 = t1 < T;

        float4 aC0, aG0, sC0, sG0, eC0, eG0, dC0, dG0;
        float4 aC1, aG1, sC1, sG1, eC1, eG1, dC1, dG1;
        if (v0) {
            int j = jx[t0], k = kx[t0], i = ix[t0];
            aC0 = ldh4(Cs + r0 * 264 + c4);
            aG0 = ldh4(Cs + r0 * 264 + 128 + c4);
            sC0 = ldh4(g_Vsrc + (size_t)j * 256 + c4);
            sG0 = ldh4(g_Vsrc + (size_t)j * 256 + 128 + c4);
            eC0 = ldh4(g_Ep + (size_t)k * 256 + c4);
            eG0 = ldh4(g_Ep + (size_t)k * 256 + 128 + c4);
            dC0 = ldh4(g_Vdst + (size_t)i * 256 + c4);
            dG0 = ldh4(g_Vdst + (size_t)i * 256 + 128 + c4);
        }
        if (v1) {
            int j = jx[t1], k = kx[t1], i = ix[t1];
            aC1 = ldh4(Cs + (r0 + 1) * 264 + c4);
            aG1 = ldh4(Cs + (r0 + 1) * 264 + 128 + c4);
            sC1 = ldh4(g_Vsrc + (size_t)j * 256 + c4);
            sG1 = ldh4(g_Vsrc + (size_t)j * 256 + 128 + c4);
            eC1 = ldh4(g_Ep + (size_t)k * 256 + c4);
            eG1 = ldh4(g_Ep + (size_t)k * 256 + 128 + c4);
            dC1 = ldh4(g_Vdst + (size_t)i * 256 + c4);
            dG1 = ldh4(g_Vdst + (size_t)i * 256 + 128 + c4);
        }

#pragma unroll
        for (int u = 0; u < 2; ++u) {
            bool v = u ? v1 : v0;
            if (!v) continue;
            int t = u ? t1 : t0;
            float4 oc = u ? f4add(f4add(aC1, sC1), f4add(eC1, dC1))
                          : f4add(f4add(aC0, sC0), f4add(eC0, dC0));
            float4 og = u ? f4add(f4add(aG1, sG1), f4add(eG1, dG1))
                          : f4add(f4add(aG0, sG0), f4add(eG0, dG0));
            __half2 hc0 = __floats2half2_rn(oc.x, oc.y);
            __half2 hc1 = __floats2half2_rn(oc.z, oc.w);
            __half2 hg0 = __floats2half2_rn(og.x, og.y);
            __half2 hg1 = __floats2half2_rn(og.z, og.w);
            uint2 uc = make_uint2(*reinterpret_cast<uint32_t*>(&hc0),
                                  *reinterpret_cast<uint32_t*>(&hc1));
            uint2 ug = make_uint2(*reinterpret_cast<uint32_t*>(&hg0),
                                  *reinterpret_cast<uint32_t*>(&hg1));
            *reinterpret_cast<uint2*>(g_A + (size_t)t * 256 + c4) = uc;
            *reinterpret_cast<uint2*>(g_A + (size_t)t * 256 + 128 + c4) = ug;
            float2 fc0 = __half22float2(hc0), fc1 = __half22float2(hc1);
            float2 fg0 = __half22float2(hg0), fg1 = __half22float2(hg1);
            sumC.x += fc0.x; sumC.y += fc0.y; sumC.z += fc1.x; sumC.w += fc1.y;
            ssqC.x += fc0.x * fc0.x; ssqC.y += fc0.y * fc0.y;
            ssqC.z += fc1.x * fc1.x; ssqC.w += fc1.y * fc1.y;
            sumG.x += fg0.x; sumG.y += fg0.y; sumG.z += fg1.x; sumG.w += fg1.y;
            ssqG.x += fg0.x * fg0.x; ssqG.y += fg0.y * fg0.y;
            ssqG.z += fg1.x * fg1.x; ssqG.w += fg1.y * fg1.y;
        }
    }

    atomicAdd(&s_sum[c4 + 0], sumC.x); atomicAdd(&s_sum[c4 + 1], sumC.y);
    atomicAdd(&s_sum[c4 + 2], sumC.z); atomicAdd(&s_sum[c4 + 3], sumC.w);
    atomicAdd(&s_ssq[c4 + 0], ssqC.x); atomicAdd(&s_ssq[c4 + 1], ssqC.y);
    atomicAdd(&s_ssq[c4 + 2], ssqC.z); atomicAdd(&s_ssq[c4 + 3], ssqC.w);
    atomicAdd(&s_sum[128 + c4 + 0], sumG.x); atomicAdd(&s_sum[128 + c4 + 1], sumG.y);
    atomicAdd(&s_sum[128 + c4 + 2], sumG.z); atomicAdd(&s_sum[128 + c4 + 3], sumG.w);
    atomicAdd(&s_ssq[128 + c4 + 0], ssqG.x); atomicAdd(&s_ssq[128 + c4 + 1], ssqG.y);
    atomicAdd(&s_ssq[128 + c4 + 2], ssqG.z); atomicAdd(&s_ssq[128 + c4 + 3], ssqG.w);
    __syncthreads();
    if (tid < 128) {
        atomicAdd(&g_stats[tid], s_sum[tid]);
        atomicAdd(&g_stats[128 + tid], s_ssq[tid]);
    } else {
        int t = tid - 128;
        atomicAdd(&g_stats[256 + t], s_sum[tid]);
        atomicAdd(&g_stats[384 + t], s_ssq[tid]);
    }
}

// ------------------------------------------------------------------
__global__ void finalize_stats(const float* __restrict__ gamC, const float* __restrict__ betC,
                               const float* __restrict__ gamG, const float* __restrict__ betG,
                               float invT) {
    int c = threadIdx.x;  // 128 threads
    float m = g_stats[c] * invT;
    float v = g_stats[128 + c] * invT - m * m;
    float a = rsqrtf(v + BN_EPS) * gamC[c];
    g_scale[c] = a;
    g_scale[128 + c] = betC[c] - m * a;

    m = g_stats[256 + c] * invT;
    v = g_stats[384 + c] * invT - m * m;
    a = rsqrtf(v + BN_EPS) * gamG[c];
    g_scale[256 + c] = a;
    g_scale[384 + c] = betG[c] - m * a;
}

// ------------------------------------------------------------------
__device__ __forceinline__ float sigf(float x) { return 1.0f / (1.0f + __expf(-x)); }

// champion version: uint2 loads per half, fp16x2 atomics, x2 unrolled.
__global__ void pass_scatter(const int* __restrict__ kx, int T) {
    const int lane = threadIdx.x & 31;
    int warp = (blockIdx.x * blockDim.x + threadIdx.x) >> 5;
    const int nw = (gridDim.x * blockDim.x) >> 5;
    const int c4 = lane * 4;

    const float4 ac = reinterpret_cast<const float4*>(g_scale)[lane];
    const float4 bc = reinterpret_cast<const float4*>(g_scale + 128)[lane];
    const float4 ag = reinterpret_cast<const float4*>(g_scale + 256)[lane];
    const float4 bg = reinterpret_cast<const float4*>(g_scale + 384)[lane];

    for (int t0 = warp * 2; t0 < T; t0 += nw * 2) {
        int t1 = t0 + 1;
        bool h1 = t1 < T;
        int k0 = kx[t0];
        int k1 = h1 ? kx[t1] : k0;

        const __half* A0 = g_A + (size_t)t0 * 256;
        const __half* A1 = g_A + (size_t)t1 * 256;
        float4 c0 = ldh4(A0 + c4), g0 = ldh4(A0 + 128 + c4);
        float4 c1, g1;
        if (h1) { c1 = ldh4(A1 + c4); g1 = ldh4(A1 + 128 + c4); }

        {
            float cnx = c0.x * ac.x + bc.x, cny = c0.y * ac.y + bc.y;
            float cnz = c0.z * ac.z + bc.z, cnw = c0.w * ac.w + bc.w;
            float gnx = g0.x * ag.x + bg.x, gny = g0.y * ag.y + bg.y;
            float gnz = g0.z * ag.z + bg.z, gnw = g0.w * ag.w + bg.w;
            __half2* dst = reinterpret_cast<__half2*>(g_seg + (size_t)k0 * 128 + c4);
            atomicAdd(dst, __floats2half2_rn(cnx * sigf(cnx) * sigf(gnx),
                                             cny * sigf(cny) * sigf(gny)));
            atomicAdd(dst + 1, __floats2half2_rn(cnz * sigf(cnz) * sigf(gnz),
                                                 cnw * sigf(cnw) * sigf(gnw)));
        }
        if (h1) {
            float cnx = c1.x * ac.x + bc.x, cny = c1.y * ac.y + bc.y;
            float cnz = c1.z * ac.z + bc.z, cnw = c1.w * ac.w + bc.w;
            float gnx = g1.x * ag.x + bg.x, gny = g1.y * ag.y + bg.y;
            float gnz = g1.z * ag.z + bg.z, gnw = g1.w * ag.w + bg.w;
            __half2* dst = reinterpret_cast<__half2*>(g_seg + (size_t)k1 * 128 + c4);
            atomicAdd(dst, __floats2half2_rn(cnx * sigf(cnx) * sigf(gnx),
                                             cny * sigf(cny) * sigf(gny)));
            atomicAdd(dst + 1, __floats2half2_rn(cnz * sigf(cnz) * sigf(gnz),
                                                 cnw * sigf(cnw) * sigf(gnw)));
        }
    }
}

// ------------------------------------------------------------------
extern "C" void kernel_launch(void* const* d_in, const int* in_sizes, int n_in,
                              void* d_out, int out_size) {
    const float* vertex = (const float*)d_in[0];
    const float* edge   = (const float*)d_in[1];
    const float* angle  = (const float*)d_in[2];
    const int* kx = (const int*)d_in[4];
    const int* jx = (const int*)d_in[5];
    const int* ix = (const int*)d_in[6];
    const float* w_cs = (const float*)d_in[7];
    const float* w_cd = (const float*)d_in[8];
    const float* w_cb = (const float*)d_in[9];
    const float* w_ca = (const float*)d_in[10];
    const float* w_gs = (const float*)d_in[11];
    const float* w_gd = (const float*)d_in[12];
    const float* w_gb = (const float*)d_in[13];
    const float* w_ga = (const float*)d_in[14];
    const float* bcg = (const float*)d_in[15];
    const float* bcb = (const float*)d_in[16];
    const float* bgg = (const float*)d_in[17];
    const float* bgb = (const float*)d_in[18];
    const float* w_out = (const float*)d_in[19];

    const int N = in_sizes[0] / 128;
    const int E = in_sizes[1] / 128;
    const int T = in_sizes[2] / 64;

    __half *pVsrc, *pVdst, *pEp, *pSeg;
    float *pWv, *pWeb, *pWan;
    cudaGetSymbolAddress((void**)&pVsrc, g_Vsrc);
    cudaGetSymbolAddress((void**)&pVdst, g_Vdst);
    cudaGetSymbolAddress((void**)&pEp, g_Ep);
    cudaGetSymbolAddress((void**)&pSeg, g_seg);
    cudaGetSymbolAddress((void**)&pWv, g_Wv);
    cudaGetSymbolAddress((void**)&pWeb, g_Web);
    cudaGetSymbolAddress((void**)&pWan, g_Wan);

    const size_t smem_gemm = 2 * 128 * 72 * sizeof(__half);                // 36864
    const size_t smem_fuse = (2 * 128 * 72 + 128 * 264) * sizeof(__half);  // 104448
    cudaFuncSetAttribute(mma_gemm<128, float, __half>,
                         cudaFuncAttributeMaxDynamicSharedMemorySize, (int)smem_gemm);
    cudaFuncSetAttribute(mma_gemm<128, __half, float>,
                         cudaFuncAttributeMaxDynamicSharedMemorySize, (int)smem_gemm);
    cudaFuncSetAttribute(mma_gemm_vertex,
                         cudaFuncAttributeMaxDynamicSharedMemorySize, (int)smem_gemm);
    cudaFuncSetAttribute(angle_fuse,
                         cudaFuncAttributeMaxDynamicSharedMemorySize, (int)smem_fuse);

    // merged preamble: zero seg + stats, pack weights (one launch)
    preamble<<<2048, 256>>>(w_cs, w_gs, w_cd, w_gd, w_cb, w_gb, w_ca, w_ga, E);

    const int gN = (N + 127) / 128;
    const int gE = (E + 127) / 128;
    const int gT = (T + 127) / 128;

    // vertex: single launch, 4 output tiles (Vsrc core|gate, Vdst core|gate)
    mma_gemm_vertex<<<dim3(gN, 4), 256, smem_gemm>>>(vertex, pWv, pVsrc, pVdst, N);
    mma_gemm<128, float, __half><<<dim3(gE, 2), 256, smem_gemm>>>(
        edge, pWeb, nullptr, pEp, E, 256);

    // fused: angle GEMM (full N=256) + gather-add + BN stats
    angle_fuse<<<gT, 256, smem_fuse>>>(angle, pWan, kx, jx, ix, T);

    finalize_stats<<<1, 128>>>(bcg, bcb, bgg, bgb, 1.0f / (float)T);

    // activation + segment scatter (fp16x2 atomics), x2 unrolled
    pass_scatter<<<1184, 256>>>(kx, T);

    // new_bond = seg(fp16) @ w_out.T + edge_feat  (fp32 output)
    mma_gemm<128, __half, float><<<dim3(gE, 1), 256, smem_gemm>>>(
        pSeg, w_out, edge, (float*)d_out, E, 128);
}

// round 17
// speedup vs baseline: 1.3960x; 1.1497x over previous
#include <cuda_runtime.h>
#include <cuda_fp16.h>
#include <cstdint>

#define BN_EPS 1e-5f
#define MAXN 100000
#define MAXE 400000
#define MAXT 1000000

// ---- scratch (allocation-free, static device globals) ----
__device__ __half g_Vsrc[(size_t)MAXN * 256];  // [N,256] = [core_src | gate_src]
__device__ __half g_Vdst[(size_t)MAXN * 256];  // [N,256] = [core_dst | gate_dst]
__device__ __half g_Ep  [(size_t)MAXE * 256];  // [E,256] = [core_bond | gate_bond]
__device__ __half g_A   [(size_t)MAXT * 256];  // [T,256] fused core|gate (pre-BN)
__device__ __half g_seg [(size_t)MAXE * 128];  // segment sums (fp16x2 atomics)
__device__ float  g_stats[512];                // sumC | ssqC | sumG | ssqG
__device__ float  g_scale[512];                // aC | bC | aG | bG
__device__ float  g_Wv [512 * 128];            // [w_core_src; w_gate_src; w_core_dst; w_gate_dst]
__device__ float  g_Web[256 * 128];            // [w_core_bond ; w_gate_bond]
__device__ float  g_Wan[256 * 64];             // [w_core_angle ; w_gate_angle]

// ------------------------------------------------------------------
// merged preamble: zero seg buffer + stats, pack all weight pairs.
// ------------------------------------------------------------------
__global__ void preamble(const float* __restrict__ cs, const float* __restrict__ gs,
                         const float* __restrict__ cd, const float* __restrict__ gd,
                         const float* __restrict__ cb, const float* __restrict__ gb,
                         const float* __restrict__ ca, const float* __restrict__ ga,
                         int E) {
    size_t n16 = (size_t)E * 16;
    size_t i = (size_t)blockIdx.x * blockDim.x + threadIdx.x;
    size_t st = (size_t)gridDim.x * blockDim.x;
    uint4 z = make_uint4(0, 0, 0, 0);
    uint4* p = reinterpret_cast<uint4*>(g_seg);
    for (size_t k = i; k < n16; k += st) p[k] = z;

    int ii = (int)i;
    if (ii < 512) g_stats[ii] = 0.f;
    if (ii < 16384) {
        g_Wv[ii] = cs[ii];           g_Wv[16384 + ii] = gs[ii];
        g_Wv[32768 + ii] = cd[ii];   g_Wv[49152 + ii] = gd[ii];
        g_Web[ii] = cb[ii];          g_Web[16384 + ii] = gb[ii];
    }
    if (ii < 8192) {
        g_Wan[ii] = ca[ii];          g_Wan[8192 + ii] = ga[ii];
    }
}

// ---- fp16 helpers ----
__device__ __forceinline__ float4 ldh4(const __half* p) {
    uint2 u = *reinterpret_cast<const uint2*>(p);
    __half2 h0 = *reinterpret_cast<__half2*>(&u.x);
    __half2 h1 = *reinterpret_cast<__half2*>(&u.y);
    float2 f0 = __half22float2(h0);
    float2 f1 = __half22float2(h1);
    return make_float4(f0.x, f0.y, f1.x, f1.y);
}
__device__ __forceinline__ float4 u2f4(uint2 u) {
    __half2 h0 = *reinterpret_cast<__half2*>(&u.x);
    __half2 h1 = *reinterpret_cast<__half2*>(&u.y);
    float2 f0 = __half22float2(h0);
    float2 f1 = __half22float2(h1);
    return make_float4(f0.x, f0.y, f1.x, f1.y);
}
__device__ __forceinline__ float4 f4add(float4 a, float4 b) {
    return make_float4(a.x + b.x, a.y + b.y, a.z + b.z, a.w + b.w);
}

// ------------------------------------------------------------------
// 128x128x64 fp16 MMA sweep; word stride 36 (72-half rows)
// ------------------------------------------------------------------
__device__ __forceinline__
void mma64(const __half* Xs, const __half* Ws, float c[4][4][4],
           int warpM, int warpN, int g, int qc) {
    const uint32_t* Xu = reinterpret_cast<const uint32_t*>(Xs);
    const uint32_t* Wu = reinterpret_cast<const uint32_t*>(Ws);
#pragma unroll
    for (int k0 = 0; k0 < 64; k0 += 16) {
        const int kw = k0 >> 1;
        uint32_t a[4][4], b[4][2];
#pragma unroll
        for (int mf = 0; mf < 4; ++mf) {
            int r = warpM * 64 + mf * 16 + g;
            a[mf][0] = Xu[r * 36 + kw + qc];
            a[mf][1] = Xu[(r + 8) * 36 + kw + qc];
            a[mf][2] = Xu[r * 36 + kw + 4 + qc];
            a[mf][3] = Xu[(r + 8) * 36 + kw + 4 + qc];
        }
#pragma unroll
        for (int nf = 0; nf < 4; ++nf) {
            int n = warpN * 32 + nf * 8 + g;
            b[nf][0] = Wu[n * 36 + kw + qc];
            b[nf][1] = Wu[n * 36 + kw + 4 + qc];
        }
#pragma unroll
        for (int mf = 0; mf < 4; ++mf)
#pragma unroll
            for (int nf = 0; nf < 4; ++nf) {
                asm volatile(
                    "mma.sync.aligned.m16n8k16.row.col.f32.f16.f16.f32 "
                    "{%0,%1,%2,%3}, {%4,%5,%6,%7}, {%8,%9}, {%0,%1,%2,%3};"
                    : "+f"(c[mf][nf][0]), "+f"(c[mf][nf][1]),
                      "+f"(c[mf][nf][2]), "+f"(c[mf][nf][3])
                    : "r"(a[mf][0]), "r"(a[mf][1]), "r"(a[mf][2]), "r"(a[mf][3]),
                      "r"(b[nf][0]), "r"(b[nf][1]));
            }
    }
}

// 64x128x64 fp16 MMA sweep (angle_fuse): warp tile 32x32
__device__ __forceinline__
void mma64x32(const __half* Xs, const __half* Ws, float c[2][4][4],
              int warpM, int warpN, int g, int qc) {
    const uint32_t* Xu = reinterpret_cast<const uint32_t*>(Xs);
    const uint32_t* Wu = reinterpret_cast<const uint32_t*>(Ws);
#pragma unroll
    for (int k0 = 0; k0 < 64; k0 += 16) {
        const int kw = k0 >> 1;
        uint32_t a[2][4], b[4][2];
#pragma unroll
        for (int mf = 0; mf < 2; ++mf) {
            int r = warpM * 32 + mf * 16 + g;
            a[mf][0] = Xu[r * 36 + kw + qc];
            a[mf][1] = Xu[(r + 8) * 36 + kw + qc];
            a[mf][2] = Xu[r * 36 + kw + 4 + qc];
            a[mf][3] = Xu[(r + 8) * 36 + kw + 4 + qc];
        }
#pragma unroll
        for (int nf = 0; nf < 4; ++nf) {
            int n = warpN * 32 + nf * 8 + g;
            b[nf][0] = Wu[n * 36 + kw + qc];
            b[nf][1] = Wu[n * 36 + kw + 4 + qc];
        }
#pragma unroll
        for (int mf = 0; mf < 2; ++mf)
#pragma unroll
            for (int nf = 0; nf < 4; ++nf) {
                asm volatile(
                    "mma.sync.aligned.m16n8k16.row.col.f32.f16.f16.f32 "
                    "{%0,%1,%2,%3}, {%4,%5,%6,%7}, {%8,%9}, {%0,%1,%2,%3};"
                    : "+f"(c[mf][nf][0]), "+f"(c[mf][nf][1]),
                      "+f"(c[mf][nf][2]), "+f"(c[mf][nf][3])
                    : "r"(a[mf][0]), "r"(a[mf][1]), "r"(a[mf][2]), "r"(a[mf][3]),
                      "r"(b[nf][0]), "r"(b[nf][1]));
            }
    }
}

// ------------------------------------------------------------------
// generic GEMM accumulate (input fp32 or fp16), 128x128 tile, BK=64 loop
// ------------------------------------------------------------------
template<int K, typename InT>
__device__ __forceinline__
void gemm_accum(const InT* __restrict__ X, const float* __restrict__ W,
                int M, int row0, int wBase, char* smemc, float c[4][4][4]) {
    constexpr int BK = 64;
    constexpr int KP = 72;
    __half* Xs = reinterpret_cast<__half*>(smemc);
    __half* Ws = Xs + 128 * KP;

    const int tid = threadIdx.x;
    const int lane = tid & 31;
    const int wid = tid >> 5;
    const int warpM = wid >> 2, warpN = wid & 3;
    const int g = lane >> 2, qc = lane & 3;

#pragma unroll
    for (int mf = 0; mf < 4; ++mf)
#pragma unroll
        for (int nf = 0; nf < 4; ++nf)
#pragma unroll
            for (int q = 0; q < 4; ++q) c[mf][nf][q] = 0.f;

    for (int kt = 0; kt < K; kt += BK) {
        for (int i = tid; i < 128 * (BK / 4); i += 256) {
            int r = i >> 4;
            int k4 = (i & 15) << 2;
            int gr = row0 + r;
            if constexpr (sizeof(InT) == 4) {
                float4 v = make_float4(0.f, 0.f, 0.f, 0.f);
                if (gr < M)
                    v = *reinterpret_cast<const float4*>(X + (size_t)gr * K + kt + k4);
                __half2 h0 = __floats2half2_rn(v.x, v.y);
                __half2 h1 = __floats2half2_rn(v.z, v.w);
                uint2 u = make_uint2(*reinterpret_cast<uint32_t*>(&h0),
                                     *reinterpret_cast<uint32_t*>(&h1));
                *reinterpret_cast<uint2*>(Xs + r * KP + k4) = u;
            } else {
                uint2 u = make_uint2(0u, 0u);
                if (gr < M)
                    u = *reinterpret_cast<const uint2*>(X + (size_t)gr * K + kt + k4);
                *reinterpret_cast<uint2*>(Xs + r * KP + k4) = u;
            }
        }
        for (int i = tid; i < 128 * (BK / 4); i += 256) {
            int r = i >> 4;
            int k4 = (i & 15) << 2;
            float4 v = *reinterpret_cast<const float4*>(W + (size_t)(wBase + r) * K + kt + k4);
            __half2 h0 = __floats2half2_rn(v.x, v.y);
            __half2 h1 = __floats2half2_rn(v.z, v.w);
            uint2 u = make_uint2(*reinterpret_cast<uint32_t*>(&h0),
                                 *reinterpret_cast<uint32_t*>(&h1));
            *reinterpret_cast<uint2*>(Ws + r * KP + k4) = u;
        }
        __syncthreads();
        mma64(Xs, Ws, c, warpM, warpN, g, qc);
        __syncthreads();
    }
}

template<int K, typename InT, typename OutT>
__global__ __launch_bounds__(256, 2)
void mma_gemm(const InT* __restrict__ X, const float* __restrict__ W,
              const float* __restrict__ Dadd, OutT* __restrict__ C,
              int M, int ldc) {
    extern __shared__ char smemc[];
    float c[4][4][4];
    const int row0 = blockIdx.x * 128;
    const int nBase = blockIdx.y * 128;
    gemm_accum<K, InT>(X, W, M, row0, nBase, smemc, c);

    const int lane = threadIdx.x & 31;
    const int wid = threadIdx.x >> 5;
    const int warpM = wid >> 2, warpN = wid & 3;
    const int g = lane >> 2, qc = lane & 3;
#pragma unroll
    for (int mf = 0; mf < 4; ++mf) {
#pragma unroll
        for (int nf = 0; nf < 4; ++nf) {
            int col = nBase + warpN * 32 + nf * 8 + qc * 2;
#pragma unroll
            for (int half = 0; half < 2; ++half) {
                int r = row0 + warpM * 64 + mf * 16 + g + half * 8;
                if (r >= M) continue;
                float ox = c[mf][nf][half * 2 + 0];
                float oy = c[mf][nf][half * 2 + 1];
                if constexpr (sizeof(OutT) == 4) {
                    if (Dadd) {
                        float2 d = *reinterpret_cast<const float2*>(
                            Dadd + (size_t)r * ldc + col);
                        ox += d.x; oy += d.y;
                    }
                    *reinterpret_cast<float2*>(
                        reinterpret_cast<float*>(C) + (size_t)r * ldc + col) =
                        make_float2(ox, oy);
                } else {
                    __half2 h = __floats2half2_rn(ox, oy);
                    *reinterpret_cast<__half2*>(
                        reinterpret_cast<__half*>(C) + (size_t)r * ldc + col) = h;
                }
            }
        }
    }
}

// merged vertex GEMM: y in 0..3 -> [Vsrc core, Vsrc gate, Vdst core, Vdst gate]
__global__ __launch_bounds__(256, 2)
void mma_gemm_vertex(const float* __restrict__ X, const float* __restrict__ W,
                     __half* __restrict__ C0, __half* __restrict__ C1, int M) {
    extern __shared__ char smemc[];
    float c[4][4][4];
    const int y = blockIdx.y;
    const int row0 = blockIdx.x * 128;
    __half* C = (y < 2) ? C0 : C1;
    const int colBase = (y & 1) * 128;
    gemm_accum<128, float>(X, W, M, row0, y * 128, smemc, c);

    const int lane = threadIdx.x & 31;
    const int wid = threadIdx.x >> 5;
    const int warpM = wid >> 2, warpN = wid & 3;
    const int g = lane >> 2, qc = lane & 3;
#pragma unroll
    for (int mf = 0; mf < 4; ++mf) {
#pragma unroll
        for (int nf = 0; nf < 4; ++nf) {
            int col = colBase + warpN * 32 + nf * 8 + qc * 2;
#pragma unroll
            for (int half = 0; half < 2; ++half) {
                int r = row0 + warpM * 64 + mf * 16 + g + half * 8;
                if (r >= M) continue;
                __half2 h = __floats2half2_rn(c[mf][nf][half * 2 + 0],
                                              c[mf][nf][half * 2 + 1]);
                *reinterpret_cast<__half2*>(C + (size_t)r * 256 + col) = h;
            }
        }
    }
}

// ------------------------------------------------------------------
// Fused angle GEMM + gather-add + BN stats. BM=64 for 3 CTA/SM occupancy.
// smem: Xs [64][72] 9216 + Ws [128][72] 18432 + Cs [64][264] 33792 = 61440 B
// Phase 3 holds gathers as raw uint2, converting at use (register budget).
// ------------------------------------------------------------------
__global__ __launch_bounds__(256, 3)
void angle_fuse(const float* __restrict__ X, const float* __restrict__ W,
                const int* __restrict__ kx, const int* __restrict__ jx,
                const int* __restrict__ ix, int T) {
    extern __shared__ char smemc[];
    __half* Xs = reinterpret_cast<__half*>(smemc);       // [64][72]
    __half* Ws = Xs + 64 * 72;                           // [128][72]
    __half* Cs = Ws + 128 * 72;                          // [64][264]
    __shared__ float s_sum[256];
    __shared__ float s_ssq[256];

    const int tid = threadIdx.x;
    const int lane = tid & 31;
    const int wid = tid >> 5;
    const int warpM = wid >> 2, warpN = wid & 3;
    const int g = lane >> 2, qc = lane & 3;
    const int row0 = blockIdx.x * 64;

    s_sum[tid] = 0.f; s_ssq[tid] = 0.f;

    // ---- load Xs (64 rows, K=64) ----
    for (int i = tid; i < 64 * 16; i += 256) {
        int r = i >> 4;
        int k4 = (i & 15) << 2;
        int gr = row0 + r;
        float4 v = make_float4(0.f, 0.f, 0.f, 0.f);
        if (gr < T) v = *reinterpret_cast<const float4*>(X + (size_t)gr * 64 + k4);
        __half2 h0 = __floats2half2_rn(v.x, v.y);
        __half2 h1 = __floats2half2_rn(v.z, v.w);
        uint2 u = make_uint2(*reinterpret_cast<uint32_t*>(&h0),
                             *reinterpret_cast<uint32_t*>(&h1));
        *reinterpret_cast<uint2*>(Xs + r * 72 + k4) = u;
    }

    float c[2][4][4];
#pragma unroll
    for (int pass = 0; pass < 2; ++pass) {
        for (int i = tid; i < 128 * 16; i += 256) {
            int r = i >> 4;
            int k4 = (i & 15) << 2;
            float4 v = *reinterpret_cast<const float4*>(
                W + (size_t)(pass * 128 + r) * 64 + k4);
            __half2 h0 = __floats2half2_rn(v.x, v.y);
            __half2 h1 = __floats2half2_rn(v.z, v.w);
            uint2 u = make_uint2(*reinterpret_cast<uint32_t*>(&h0),
                                 *reinterpret_cast<uint32_t*>(&h1));
            *reinterpret_cast<uint2*>(Ws + r * 72 + k4) = u;
        }
        __syncthreads();

#pragma unroll
        for (int mf = 0; mf < 2; ++mf)
#pragma unroll
            for (int nf = 0; nf < 4; ++nf)
#pragma unroll
                for (int q = 0; q < 4; ++q) c[mf][nf][q] = 0.f;
        mma64x32(Xs, Ws, c, warpM, warpN, g, qc);

#pragma unroll
        for (int mf = 0; mf < 2; ++mf) {
#pragma unroll
            for (int nf = 0; nf < 4; ++nf) {
                int col = pass * 128 + warpN * 32 + nf * 8 + qc * 2;
#pragma unroll
                for (int half = 0; half < 2; ++half) {
                    int r = warpM * 32 + mf * 16 + g + half * 8;
                    __half2 h = __floats2half2_rn(c[mf][nf][half * 2 + 0],
                                                  c[mf][nf][half * 2 + 1]);
                    *reinterpret_cast<__half2*>(Cs + r * 264 + col) = h;
                }
            }
        }
        __syncthreads();
    }

    // ---- phase 3: warp-per-row gather-add, x2 rows, deferred conversion ----
    const int c4 = lane * 4;
    float4 sumC = make_float4(0, 0, 0, 0), ssqC = make_float4(0, 0, 0, 0);
    float4 sumG = make_float4(0, 0, 0, 0), ssqG = make_float4(0, 0, 0, 0);

    for (int rr = 0; rr < 8; rr += 2) {
        int r0 = wid * 8 + rr;
        int t0 = row0 + r0;
        int t1 = t0 + 1;
        bool v0 = t0 < T, v1 = t1 < T;

        uint2 aC0, aG0, sC0, sG0, eC0, eG0, dC0, dG0;
        uint2 aC1, aG1, sC1, sG1, eC1, eG1, dC1, dG1;
        if (v0) {
            int j = jx[t0], k = kx[t0], i = ix[t0];
            aC0 = *reinterpret_cast<const uint2*>(Cs + r0 * 264 + c4);
            aG0 = *reinterpret_cast<const uint2*>(Cs + r0 * 264 + 128 + c4);
            sC0 = *reinterpret_cast<const uint2*>(g_Vsrc + (size_t)j * 256 + c4);
            sG0 = *reinterpret_cast<const uint2*>(g_Vsrc + (size_t)j * 256 + 128 + c4);
            eC0 = *reinterpret_cast<const uint2*>(g_Ep + (size_t)k * 256 + c4);
            eG0 = *reinterpret_cast<const uint2*>(g_Ep + (size_t)k * 256 + 128 + c4);
            dC0 = *reinterpret_cast<const uint2*>(g_Vdst + (size_t)i * 256 + c4);
            dG0 = *reinterpret_cast<const uint2*>(g_Vdst + (size_t)i * 256 + 128 + c4);
        }
        if (v1) {
            int j = jx[t1], k = kx[t1], i = ix[t1];
            aC1 = *reinterpret_cast<const uint2*>(Cs + (r0 + 1) * 264 + c4);
            aG1 = *reinterpret_cast<const uint2*>(Cs + (r0 + 1) * 264 + 128 + c4);
            sC1 = *reinterpret_cast<const uint2*>(g_Vsrc + (size_t)j * 256 + c4);
            sG1 = *reinterpret_cast<const uint2*>(g_Vsrc + (size_t)j * 256 + 128 + c4);
            eC1 = *reinterpret_cast<const uint2*>(g_Ep + (size_t)k * 256 + c4);
            eG1 = *reinterpret_cast<const uint2*>(g_Ep + (size_t)k * 256 + 128 + c4);
            dC1 = *reinterpret_cast<const uint2*>(g_Vdst + (size_t)i * 256 + c4);
            dG1 = *reinterpret_cast<const uint2*>(g_Vdst + (size_t)i * 256 + 128 + c4);
        }

        if (v0) {
            float4 oc = f4add(f4add(u2f4(aC0), u2f4(sC0)),
                              f4add(u2f4(eC0), u2f4(dC0)));
            float4 og = f4add(f4add(u2f4(aG0), u2f4(sG0)),
                              f4add(u2f4(eG0), u2f4(dG0)));
            __half2 hc0 = __floats2half2_rn(oc.x, oc.y);
            __half2 hc1 = __floats2half2_rn(oc.z, oc.w);
            __half2 hg0 = __floats2half2_rn(og.x, og.y);
            __half2 hg1 = __floats2half2_rn(og.z, og.w);
            uint2 uc = make_uint2(*reinterpret_cast<uint32_t*>(&hc0),
                                  *reinterpret_cast<uint32_t*>(&hc1));
            uint2 ug = make_uint2(*reinterpret_cast<uint32_t*>(&hg0),
                                  *reinterpret_cast<uint32_t*>(&hg1));
            *reinterpret_cast<uint2*>(g_A + (size_t)t0 * 256 + c4) = uc;
            *reinterpret_cast<uint2*>(g_A + (size_t)t0 * 256 + 128 + c4) = ug;
            float2 fc0 = __half22float2(hc0), fc1 = __half22float2(hc1);
            float2 fg0 = __half22float2(hg0), fg1 = __half22float2(hg1);
            sumC.x += fc0.x; sumC.y += fc0.y; sumC.z += fc1.x; sumC.w += fc1.y;
            ssqC.x += fc0.x * fc0.x; ssqC.y += fc0.y * fc0.y;
            ssqC.z += fc1.x * fc1.x; ssqC.w += fc1.y * fc1.y;
            sumG.x += fg0.x; sumG.y += fg0.y; sumG.z += fg1.x; sumG.w += fg1.y;
            ssqG.x += fg0.x * fg0.x; ssqG.y += fg0.y * fg0.y;
            ssqG.z += fg1.x * fg1.x; ssqG.w += fg1.y * fg1.y;
        }
        if (v1) {
            float4 oc = f4add(f4add(u2f4(aC1), u2f4(sC1)),
                              f4add(u2f4(eC1), u2f4(dC1)));
            float4 og = f4add(f4add(u2f4(aG1), u2f4(sG1)),
                              f4add(u2f4(eG1), u2f4(dG1)));
            __half2 hc0 = __floats2half2_rn(oc.x, oc.y);
            __half2 hc1 = __floats2half2_rn(oc.z, oc.w);
            __half2 hg0 = __floats2half2_rn(og.x, og.y);
            __half2 hg1 = __floats2half2_rn(og.z, og.w);
            uint2 uc = make_uint2(*reinterpret_cast<uint32_t*>(&hc0),
                                  *reinterpret_cast<uint32_t*>(&hc1));
            uint2 ug = make_uint2(*reinterpret_cast<uint32_t*>(&hg0),
                                  *reinterpret_cast<uint32_t*>(&hg1));
            *reinterpret_cast<uint2*>(g_A + (size_t)t1 * 256 + c4) = uc;
            *reinterpret_cast<uint2*>(g_A + (size_t)t1 * 256 + 128 + c4) = ug;
            float2 fc0 = __half22float2(hc0), fc1 = __half22float2(hc1);
            float2 fg0 = __half22float2(hg0), fg1 = __half22float2(hg1);
            sumC.x += fc0.x; sumC.y += fc0.y; sumC.z += fc1.x; sumC.w += fc1.y;
            ssqC.x += fc0.x * fc0.x; ssqC.y += fc0.y * fc0.y;
            ssqC.z += fc1.x * fc1.x; ssqC.w += fc1.y * fc1.y;
            sumG.x += fg0.x; sumG.y += fg0.y; sumG.z += fg1.x; sumG.w += fg1.y;
            ssqG.x += fg0.x * fg0.x; ssqG.y += fg0.y * fg0.y;
            ssqG.z += fg1.x * fg1.x; ssqG.w += fg1.y * fg1.y;
        }
    }

    atomicAdd(&s_sum[c4 + 0], sumC.x); atomicAdd(&s_sum[c4 + 1], sumC.y);
    atomicAdd(&s_sum[c4 + 2], sumC.z); atomicAdd(&s_sum[c4 + 3], sumC.w);
    atomicAdd(&s_ssq[c4 + 0], ssqC.x); atomicAdd(&s_ssq[c4 + 1], ssqC.y);
    atomicAdd(&s_ssq[c4 + 2], ssqC.z); atomicAdd(&s_ssq[c4 + 3], ssqC.w);
    atomicAdd(&s_sum[128 + c4 + 0], sumG.x); atomicAdd(&s_sum[128 + c4 + 1], sumG.y);
    atomicAdd(&s_sum[128 + c4 + 2], sumG.z); atomicAdd(&s_sum[128 + c4 + 3], sumG.w);
    atomicAdd(&s_ssq[128 + c4 + 0], ssqG.x); atomicAdd(&s_ssq[128 + c4 + 1], ssqG.y);
    atomicAdd(&s_ssq[128 + c4 + 2], ssqG.z); atomicAdd(&s_ssq[128 + c4 + 3], ssqG.w);
    __syncthreads();
    if (tid < 128) {
        atomicAdd(&g_stats[tid], s_sum[tid]);
        atomicAdd(&g_stats[128 + tid], s_ssq[tid]);
    } else {
        int t = tid - 128;
        atomicAdd(&g_stats[256 + t], s_sum[tid]);
        atomicAdd(&g_stats[384 + t], s_ssq[tid]);
    }
}

// ------------------------------------------------------------------
__global__ void finalize_stats(const float* __restrict__ gamC, const float* __restrict__ betC,
                               const float* __restrict__ gamG, const float* __restrict__ betG,
                               float invT) {
    int c = threadIdx.x;  // 128 threads
    float m = g_stats[c] * invT;
    float v = g_stats[128 + c] * invT - m * m;
    float a = rsqrtf(v + BN_EPS) * gamC[c];
    g_scale[c] = a;
    g_scale[128 + c] = betC[c] - m * a;

    m = g_stats[256 + c] * invT;
    v = g_stats[384 + c] * invT - m * m;
    a = rsqrtf(v + BN_EPS) * gamG[c];
    g_scale[256 + c] = a;
    g_scale[384 + c] = betG[c] - m * a;
}

// ------------------------------------------------------------------
__device__ __forceinline__ float sigf(float x) { return 1.0f / (1.0f + __expf(-x)); }

// champion version: uint2 loads per half, fp16x2 atomics, x2 unrolled.
__global__ void pass_scatter(const int* __restrict__ kx, int T) {
    const int lane = threadIdx.x & 31;
    int warp = (blockIdx.x * blockDim.x + threadIdx.x) >> 5;
    const int nw = (gridDim.x * blockDim.x) >> 5;
    const int c4 = lane * 4;

    const float4 ac = reinterpret_cast<const float4*>(g_scale)[lane];
    const float4 bc = reinterpret_cast<const float4*>(g_scale + 128)[lane];
    const float4 ag = reinterpret_cast<const float4*>(g_scale + 256)[lane];
    const float4 bg = reinterpret_cast<const float4*>(g_scale + 384)[lane];

    for (int t0 = warp * 2; t0 < T; t0 += nw * 2) {
        int t1 = t0 + 1;
        bool h1 = t1 < T;
        int k0 = kx[t0];
        int k1 = h1 ? kx[t1] : k0;

        const __half* A0 = g_A + (size_t)t0 * 256;
        const __half* A1 = g_A + (size_t)t1 * 256;
        float4 c0 = ldh4(A0 + c4), g0 = ldh4(A0 + 128 + c4);
        float4 c1, g1;
        if (h1) { c1 = ldh4(A1 + c4); g1 = ldh4(A1 + 128 + c4); }

        {
            float cnx = c0.x * ac.x + bc.x, cny = c0.y * ac.y + bc.y;
            float cnz = c0.z * ac.z + bc.z, cnw = c0.w * ac.w + bc.w;
            float gnx = g0.x * ag.x + bg.x, gny = g0.y * ag.y + bg.y;
            float gnz = g0.z * ag.z + bg.z, gnw = g0.w * ag.w + bg.w;
            __half2* dst = reinterpret_cast<__half2*>(g_seg + (size_t)k0 * 128 + c4);
            atomicAdd(dst, __floats2half2_rn(cnx * sigf(cnx) * sigf(gnx),
                                             cny * sigf(cny) * sigf(gny)));
            atomicAdd(dst + 1, __floats2half2_rn(cnz * sigf(cnz) * sigf(gnz),
                                                 cnw * sigf(cnw) * sigf(gnw)));
        }
        if (h1) {
            float cnx = c1.x * ac.x + bc.x, cny = c1.y * ac.y + bc.y;
            float cnz = c1.z * ac.z + bc.z, cnw = c1.w * ac.w + bc.w;
            float gnx = g1.x * ag.x + bg.x, gny = g1.y * ag.y + bg.y;
            float gnz = g1.z * ag.z + bg.z, gnw = g1.w * ag.w + bg.w;
            __half2* dst = reinterpret_cast<__half2*>(g_seg + (size_t)k1 * 128 + c4);
            atomicAdd(dst, __floats2half2_rn(cnx * sigf(cnx) * sigf(gnx),
                                             cny * sigf(cny) * sigf(gny)));
            atomicAdd(dst + 1, __floats2half2_rn(cnz * sigf(cnz) * sigf(gnz),
                                                 cnw * sigf(cnw) * sigf(gnw)));
        }
    }
}

// ------------------------------------------------------------------
extern "C" void kernel_launch(void* const* d_in, const int* in_sizes, int n_in,
                              void* d_out, int out_size) {
    const float* vertex = (const float*)d_in[0];
    const float* edge   = (const float*)d_in[1];
    const float* angle  = (const float*)d_in[2];
    const int* kx = (const int*)d_in[4];
    const int* jx = (const int*)d_in[5];
    const int* ix = (const int*)d_in[6];
    const float* w_cs = (const float*)d_in[7];
    const float* w_cd = (const float*)d_in[8];
    const float* w_cb = (const float*)d_in[9];
    const float* w_ca = (const float*)d_in[10];
    const float* w_gs = (const float*)d_in[11];
    const float* w_gd = (const float*)d_in[12];
    const float* w_gb = (const float*)d_in[13];
    const float* w_ga = (const float*)d_in[14];
    const float* bcg = (const float*)d_in[15];
    const float* bcb = (const float*)d_in[16];
    const float* bgg = (const float*)d_in[17];
    const float* bgb = (const float*)d_in[18];
    const float* w_out = (const float*)d_in[19];

    const int N = in_sizes[0] / 128;
    const int E = in_sizes[1] / 128;
    const int T = in_sizes[2] / 64;

    __half *pVsrc, *pVdst, *pEp, *pSeg;
    float *pWv, *pWeb, *pWan;
    cudaGetSymbolAddress((void**)&pVsrc, g_Vsrc);
    cudaGetSymbolAddress((void**)&pVdst, g_Vdst);
    cudaGetSymbolAddress((void**)&pEp, g_Ep);
    cudaGetSymbolAddress((void**)&pSeg, g_seg);
    cudaGetSymbolAddress((void**)&pWv, g_Wv);
    cudaGetSymbolAddress((void**)&pWeb, g_Web);
    cudaGetSymbolAddress((void**)&pWan, g_Wan);

    const size_t smem_gemm = 2 * 128 * 72 * sizeof(__half);                // 36864
    const size_t smem_fuse = (64 * 72 + 128 * 72 + 64 * 264) * sizeof(__half);  // 61440
    cudaFuncSetAttribute(mma_gemm<128, float, __half>,
                         cudaFuncAttributeMaxDynamicSharedMemorySize, (int)smem_gemm);
    cudaFuncSetAttribute(mma_gemm<128, __half, float>,
                         cudaFuncAttributeMaxDynamicSharedMemorySize, (int)smem_gemm);
    cudaFuncSetAttribute(mma_gemm_vertex,
                         cudaFuncAttributeMaxDynamicSharedMemorySize, (int)smem_gemm);
    cudaFuncSetAttribute(angle_fuse,
                         cudaFuncAttributeMaxDynamicSharedMemorySize, (int)smem_fuse);

    // merged preamble: zero seg + stats, pack weights (one launch)
    preamble<<<2048, 256>>>(w_cs, w_gs, w_cd, w_gd, w_cb, w_gb, w_ca, w_ga, E);

    const int gN = (N + 127) / 128;
    const int gE = (E + 127) / 128;
    const int gT = (T + 63) / 64;

    // vertex: single launch, 4 output tiles (Vsrc core|gate, Vdst core|gate)
    mma_gemm_vertex<<<dim3(gN, 4), 256, smem_gemm>>>(vertex, pWv, pVsrc, pVdst, N);
    mma_gemm<128, float, __half><<<dim3(gE, 2), 256, smem_gemm>>>(
        edge, pWeb, nullptr, pEp, E, 256);

    // fused: angle GEMM (BM=64, 3 CTA/SM) + gather-add + BN stats
    angle_fuse<<<gT, 256, smem_fuse>>>(angle, pWan, kx, jx, ix, T);

    finalize_stats<<<1, 128>>>(bcg, bcb, bgg, bgb, 1.0f / (float)T);

    // activation + segment scatter (fp16x2 atomics), x2 unrolled
    pass_scatter<<<1184, 256>>>(kx, T);

    // new_bond = seg(fp16) @ w_out.T + edge_feat  (fp32 output)
    mma_gemm<128, __half, float><<<dim3(gE, 1), 256, smem_gemm>>>(
        pSeg, w_out, edge, (float*)d_out, E, 128);
}